// round 1
// baseline (speedup 1.0000x reference)
#include <cuda_runtime.h>
#include <cuda_bf16.h>

// Problem constants (fixed by the reference setup):
//   B=32 batches, K=16 control points, E=K+3=19, C=3 channels, H=W=sqrt(N)
#define BATCH 32
#define KPTS  16
#define EDIM  19
#define EPAD  20   // pad to multiple of 4 for float4 shared reads

// Scratch for TPS coefficients (B x 2 x EPAD). __device__ global: no allocs.
__device__ float g_coeff[BATCH * 2 * EPAD];

// ---------------------------------------------------------------------------
// Kernel 1: coeff[b,p,e] = sum_k (src[p,k] + off[b, p*K+k]) * L_inv[e, 3+k]
// Tiny: 32*2*19 = 1216 outputs.
// ---------------------------------------------------------------------------
__global__ void tps_coeff_kernel(const float* __restrict__ dest_offsets,
                                 const float* __restrict__ L_inv,
                                 const float* __restrict__ src) {
    int i = blockIdx.x * blockDim.x + threadIdx.x;
    if (i >= BATCH * 2 * EPAD) return;
    int e = i % EPAD;
    int p = (i / EPAD) & 1;
    int b = i / (2 * EPAD);
    float acc = 0.0f;
    if (e < EDIM) {
#pragma unroll
        for (int k = 0; k < KPTS; k++) {
            float d = src[p * KPTS + k] + dest_offsets[b * 2 * KPTS + p * KPTS + k];
            acc = fmaf(d, L_inv[e * EDIM + 3 + k], acc);
        }
    }
    g_coeff[i] = acc;
}

// ---------------------------------------------------------------------------
// Kernel 2: one thread per output pixel n; loop over all B batches so the
// 19-float right_mat column is read exactly once from HBM per pixel.
// ---------------------------------------------------------------------------
__global__ void __launch_bounds__(256)
tps_sample_kernel(const float* __restrict__ img,
                  const float* __restrict__ rm,
                  float* __restrict__ out,
                  int N, int H, int W) {
    __shared__ float sc[BATCH * 2 * EPAD];   // 5 KB, broadcast reads
    for (int i = threadIdx.x; i < BATCH * 2 * EPAD; i += blockDim.x)
        sc[i] = g_coeff[i];
    __syncthreads();

    int n = blockIdx.x * blockDim.x + threadIdx.x;
    if (n >= N) return;

    // right_mat column for this pixel (rows are coalesced across the warp)
    float r[EPAD];
#pragma unroll
    for (int e = 0; e < EDIM; e++) r[e] = __ldg(&rm[(size_t)e * N + n]);
    r[EDIM] = 0.0f;

    const float fW = (float)W, fH = (float)H;
    const int   Wm1 = W - 1,   Hm1 = H - 1;

#pragma unroll 1
    for (int b = 0; b < BATCH; b++) {
        const float4* cb = reinterpret_cast<const float4*>(sc + b * 2 * EPAD);
        float x = 0.0f, y = 0.0f;
#pragma unroll
        for (int q = 0; q < EPAD / 4; q++) {
            float4 c = cb[q];
            x = fmaf(c.x, r[4 * q + 0], x);
            x = fmaf(c.y, r[4 * q + 1], x);
            x = fmaf(c.z, r[4 * q + 2], x);
            x = fmaf(c.w, r[4 * q + 3], x);
        }
#pragma unroll
        for (int q = 0; q < EPAD / 4; q++) {
            float4 c = cb[EPAD / 4 + q];
            y = fmaf(c.x, r[4 * q + 0], y);
            y = fmaf(c.y, r[4 * q + 1], y);
            y = fmaf(c.z, r[4 * q + 2], y);
            y = fmaf(c.w, r[4 * q + 3], y);
        }

        // map [-1,1] -> pixel coords, truncate (matches jnp astype(int32)),
        // clip, then weights from the CLIPPED corners (matches reference).
        x = 0.5f * (x + 1.0f) * fW;
        y = 0.5f * (y + 1.0f) * fH;
        int x0 = (int)x, y0 = (int)y;
        int x1 = x0 + 1, y1 = y0 + 1;
        x0 = min(max(x0, 0), Wm1);
        x1 = min(max(x1, 0), Wm1);
        y0 = min(max(y0, 0), Hm1);
        y1 = min(max(y1, 0), Hm1);
        float x0f = (float)x0, x1f = (float)x1;
        float y0f = (float)y0, y1f = (float)y1;
        float wa = (x1f - x) * (y1f - y);
        float wb = (x1f - x) * (y - y0f);
        float wc = (x - x0f) * (y1f - y);
        float wd = (x - x0f) * (y - y0f);

        const float* base = img + (size_t)b * H * W * 3;
        const float* pa = base + ((size_t)y0 * W + x0) * 3;
        const float* pb = base + ((size_t)y1 * W + x0) * 3;
        const float* pc = base + ((size_t)y0 * W + x1) * 3;
        const float* pd = base + ((size_t)y1 * W + x1) * 3;

        float* o = out + ((size_t)b * N + n) * 3;
#pragma unroll
        for (int c = 0; c < 3; c++) {
            o[c] = wa * __ldg(pa + c) + wb * __ldg(pb + c)
                 + wc * __ldg(pc + c) + wd * __ldg(pd + c);
        }
    }
}

// ---------------------------------------------------------------------------
// Inputs (metadata order):
//  [0] image        (B,H,W,C) f32
//  [1] dest_offsets (B, 2K)   f32
//  [2] right_mat    (E, N)    f32
//  [3] L_inv        (E, E)    f32
//  [4] source_pts   (2, K)    f32
// Output: (B,H,W,C) f32
// ---------------------------------------------------------------------------
extern "C" void kernel_launch(void* const* d_in, const int* in_sizes, int n_in,
                              void* d_out, int out_size) {
    const float* img  = (const float*)d_in[0];
    const float* offs = (const float*)d_in[1];
    const float* rm   = (const float*)d_in[2];
    const float* linv = (const float*)d_in[3];
    const float* src  = (const float*)d_in[4];
    float* out = (float*)d_out;

    int N = in_sizes[2] / EDIM;           // out pixels per batch
    // H = W = sqrt(N) (square grid, ds=(1,1))
    int W = 1;
    while ((long long)(W + 1) * (W + 1) <= (long long)N) W++;
    int H = N / W;

    tps_coeff_kernel<<<(BATCH * 2 * EPAD + 255) / 256, 256>>>(offs, linv, src);

    int threads = 256;
    int blocks = (N + threads - 1) / threads;
    tps_sample_kernel<<<blocks, threads>>>(img, rm, out, N, H, W);
}